// round 15
// baseline (speedup 1.0000x reference)
#include <cuda_runtime.h>
#include <cuda_bf16.h>
#include <cstdint>

#ifndef THR
#define THR 0.3f
#endif

// FINAL kernel (best of 14 rounds; wall 53.63us = certified steady-state DRAM
// floor: 320 MB irreducible traffic at ~5.96 TB/s sustained).
// Flat grid, 512 threads / 2048 rows per CTA.
//   loads  : warp-contiguous LDG.128 (each warp wavefront = 4 full 128B lines)
//   compute: 2 FMAs + selects per row (compute pipes <8% busy)
//   stores : output tile assembled in smem, shipped with ONE 24 KB
//            cp.async.bulk (TMA) per CTA, evict_first L2 policy.
__global__ void __launch_bounds__(512) weighting_router_final(
    const float4* __restrict__ xin,   // N/2 float4 (each float4 = 2 rows)
    float* __restrict__ out)          // 3N floats
{
    __shared__ __align__(128) float so[6144];   // 2048 rows * 3 = 24 KB

    const int tid = threadIdx.x;
    const long long blk = blockIdx.x;

    // ---- coalesced loads: warp spans 512B contiguous per LDG.128 ----
    const float4* src = xin + blk * 1024;       // 1024 float4 = 2048 rows
    float4 a = src[tid];                        // rows 2*tid,      2*tid+1
    float4 b = src[tid + 512];                  // rows 2*tid+1024, 2*tid+1025

    const float inv_hi = 1.0f / (1.0f - THR);   // 1/0.7
    const float inv_lo = 1.0f / THR;            // 1/0.3

    float h[4] = {a.x, a.z, b.x, b.z};
    float o[12];

#pragma unroll
    for (int i = 0; i < 4; i++) {
        float hv = h[i];
        bool hi = (hv >= THR);
        o[3 * i + 0] = hi ? (hv - THR) * inv_hi : 0.0f;
        o[3 * i + 1] = hi ? 0.0f : (THR - hv) * inv_lo;
        o[3 * i + 2] = hi ? (1.0f - hv) * inv_hi : hv * inv_lo;
    }

    float2* so2 = (float2*)so;
#pragma unroll
    for (int j = 0; j < 3; j++)
        so2[3 * tid + j]        = make_float2(o[2 * j],     o[2 * j + 1]);
#pragma unroll
    for (int j = 0; j < 3; j++)
        so2[3 * tid + 1536 + j] = make_float2(o[6 + 2 * j], o[6 + 2 * j + 1]);

    __syncthreads();

    // ---- single bulk TMA store with evict-first L2 policy ----
    if (tid == 0) {
        float* dst = out + blk * 6144;
        uint32_t so_addr = (uint32_t)__cvta_generic_to_shared(so);
        uint64_t pol_st;
        asm volatile("createpolicy.fractional.L2::evict_first.b64 %0, 1.0;"
                     : "=l"(pol_st));
        asm volatile("fence.proxy.async.shared::cta;" ::: "memory");
        asm volatile(
            "cp.async.bulk.global.shared::cta.bulk_group.L2::cache_hint "
            "[%0], [%1], %2, %3;"
            :: "l"(dst), "r"(so_addr), "r"(24576u), "l"(pol_st) : "memory");
        asm volatile("cp.async.bulk.commit_group;" ::: "memory");
        asm volatile("cp.async.bulk.wait_group 0;" ::: "memory");
    }
}

// Tail handler for rows not covered by the block-tiled kernel (n % 2048 != 0).
__global__ void weighting_router_tail(
    const float* __restrict__ x,
    float* __restrict__ out,
    int start_row, int n_rows)
{
    int i = start_row + blockIdx.x * blockDim.x + threadIdx.x;
    if (i >= n_rows) return;

    const float inv_hi = 1.0f / (1.0f - THR);
    const float inv_lo = 1.0f / THR;

    float hv = x[2 * i];
    bool hi = (hv >= THR);
    out[3 * i + 0] = hi ? (hv - THR) * inv_hi : 0.0f;
    out[3 * i + 1] = hi ? 0.0f : (THR - hv) * inv_lo;
    out[3 * i + 2] = hi ? (1.0f - hv) * inv_hi : hv * inv_lo;
}

extern "C" void kernel_launch(void* const* d_in, const int* in_sizes, int n_in,
                              void* d_out, int out_size)
{
    const float* x = (const float*)d_in[0];
    float* out = (float*)d_out;

    int n_rows = in_sizes[0] / 2;     // x is (N, 2)
    int n_blocks = n_rows / 2048;

    if (n_blocks > 0) {
        weighting_router_final<<<n_blocks, 512>>>(
            (const float4*)x, out);
    }

    int done = n_blocks * 2048;
    int rem = n_rows - done;
    if (rem > 0) {
        int threads = 128;
        int blocks = (rem + threads - 1) / threads;
        weighting_router_tail<<<blocks, threads>>>(x, out, done, n_rows);
    }
}

// round 16
// speedup vs baseline: 1.0048x; 1.0048x over previous
#include <cuda_runtime.h>
#include <cuda_bf16.h>
#include <cstdint>

#ifndef THR
#define THR 0.3f
#endif

// Large-tile probe: 1024 threads / 4096 rows / 48 KB tile per CTA.
// Same data path as the certified-floor kernel (warp-contiguous LDG.128 ->
// compute -> smem -> one cp.async.bulk store, evict_first), but half the
// number of TMA transactions, each a longer contiguous burst.
// 2 CTAs/SM (2048 thr, 96 KB smem) keeps the SM fully populated.
__global__ void __launch_bounds__(1024) weighting_router_4k(
    const float4* __restrict__ xin,   // N/2 float4 (each float4 = 2 rows)
    float* __restrict__ out)          // 3N floats
{
    __shared__ __align__(128) float so[12288];  // 4096 rows * 3 = 48 KB

    const int tid = threadIdx.x;
    const long long blk = blockIdx.x;

    // ---- coalesced loads: warp spans 512B contiguous per LDG.128 ----
    const float4* src = xin + blk * 2048;       // 2048 float4 = 4096 rows
    float4 a = src[tid];                        // rows 2*tid,      2*tid+1
    float4 b = src[tid + 1024];                 // rows 2*tid+2048, 2*tid+2049

    const float inv_hi = 1.0f / (1.0f - THR);   // 1/0.7
    const float inv_lo = 1.0f / THR;            // 1/0.3

    float h[4] = {a.x, a.z, b.x, b.z};
    float o[12];

#pragma unroll
    for (int i = 0; i < 4; i++) {
        float hv = h[i];
        bool hi = (hv >= THR);
        o[3 * i + 0] = hi ? (hv - THR) * inv_hi : 0.0f;
        o[3 * i + 1] = hi ? 0.0f : (THR - hv) * inv_lo;
        o[3 * i + 2] = hi ? (1.0f - hv) * inv_hi : hv * inv_lo;
    }

    // rows 2*tid,2*tid+1     -> f2 idx 3*tid
    // rows 2*tid+2048,+2049  -> f2 idx 3*tid + 3072
    float2* so2 = (float2*)so;
#pragma unroll
    for (int j = 0; j < 3; j++)
        so2[3 * tid + j]        = make_float2(o[2 * j],     o[2 * j + 1]);
#pragma unroll
    for (int j = 0; j < 3; j++)
        so2[3 * tid + 3072 + j] = make_float2(o[6 + 2 * j], o[6 + 2 * j + 1]);

    __syncthreads();

    // ---- single 48 KB bulk TMA store with evict-first L2 policy ----
    if (tid == 0) {
        float* dst = out + blk * 12288;
        uint32_t so_addr = (uint32_t)__cvta_generic_to_shared(so);
        uint64_t pol_st;
        asm volatile("createpolicy.fractional.L2::evict_first.b64 %0, 1.0;"
                     : "=l"(pol_st));
        asm volatile("fence.proxy.async.shared::cta;" ::: "memory");
        asm volatile(
            "cp.async.bulk.global.shared::cta.bulk_group.L2::cache_hint "
            "[%0], [%1], %2, %3;"
            :: "l"(dst), "r"(so_addr), "r"(49152u), "l"(pol_st) : "memory");
        asm volatile("cp.async.bulk.commit_group;" ::: "memory");
        asm volatile("cp.async.bulk.wait_group 0;" ::: "memory");
    }
}

// Tail handler for rows not covered by the block-tiled kernel (n % 4096 != 0).
__global__ void weighting_router_tail(
    const float* __restrict__ x,
    float* __restrict__ out,
    int start_row, int n_rows)
{
    int i = start_row + blockIdx.x * blockDim.x + threadIdx.x;
    if (i >= n_rows) return;

    const float inv_hi = 1.0f / (1.0f - THR);
    const float inv_lo = 1.0f / THR;

    float hv = x[2 * i];
    bool hi = (hv >= THR);
    out[3 * i + 0] = hi ? (hv - THR) * inv_hi : 0.0f;
    out[3 * i + 1] = hi ? 0.0f : (THR - hv) * inv_lo;
    out[3 * i + 2] = hi ? (1.0f - hv) * inv_hi : hv * inv_lo;
}

extern "C" void kernel_launch(void* const* d_in, const int* in_sizes, int n_in,
                              void* d_out, int out_size)
{
    const float* x = (const float*)d_in[0];
    float* out = (float*)d_out;

    int n_rows = in_sizes[0] / 2;     // x is (N, 2)
    int n_blocks = n_rows / 4096;

    if (n_blocks > 0) {
        weighting_router_4k<<<n_blocks, 1024>>>(
            (const float4*)x, out);
    }

    int done = n_blocks * 4096;
    int rem = n_rows - done;
    if (rem > 0) {
        int threads = 128;
        int blocks = (rem + threads - 1) / threads;
        weighting_router_tail<<<blocks, threads>>>(x, out, done, n_rows);
    }
}